// round 1
// baseline (speedup 1.0000x reference)
#include <cuda_runtime.h>
#include <math.h>

#define T_TOK   32768
#define H_DIM   256
#define F_DIM   512
#define E_NUM   16
#define ROWS_PAD 67584            // 2*T + E*128 (worst-case segment padding), 128-aligned
#define MAXT    (ROWS_PAD / 128)  // 528 m-tiles

// ---------------- scratch (static device arrays; no allocation) ----------------
__device__ int   g_counts[E_NUM];
__device__ int   g_cursor[E_NUM];
__device__ int   g_poff[E_NUM + 1];
__device__ int   g_eid[T_TOK * 2];
__device__ float g_gw[T_TOK * 2];
__device__ int   g_rowtok[ROWS_PAD];      // permuted row -> token (-1 = padding)
__device__ int   g_tokrow[T_TOK * 2];     // token,slot -> permuted row
__device__ float g_h[(size_t)ROWS_PAD * F_DIM];    // hidden activations (relu(xW1+b1))
__device__ float g_eout[(size_t)ROWS_PAD * H_DIM]; // expert outputs (hW2+b2)

// ---------------- init ----------------
__global__ void k_init() {
    int i = blockIdx.x * blockDim.x + threadIdx.x;
    if (i < ROWS_PAD) g_rowtok[i] = -1;
    if (i < E_NUM) { g_counts[i] = 0; g_cursor[i] = 0; }
}

// ---------------- gating: logits, top-2, softmax weights ----------------
__global__ void k_gate(const float* __restrict__ x, const float* __restrict__ gw,
                       const float* __restrict__ gb) {
    __shared__ float sgw[H_DIM * 17];  // padded to kill bank conflicts
    int tid = threadIdx.x;
    for (int i = tid; i < H_DIM * E_NUM; i += 256) {
        int h = i >> 4, e = i & 15;
        sgw[h * 17 + e] = gw[i];
    }
    __syncthreads();
    int warp = tid >> 5, lane = tid & 31;
    int t = blockIdx.x * 8 + warp;

    float acc[E_NUM];
#pragma unroll
    for (int e = 0; e < E_NUM; e++) acc[e] = 0.f;
    const float* xr = x + (size_t)t * H_DIM;
#pragma unroll
    for (int c = 0; c < H_DIM / 32; c++) {
        int h = c * 32 + lane;
        float xv = xr[h];
#pragma unroll
        for (int e = 0; e < E_NUM; e++) acc[e] += xv * sgw[h * 17 + e];
    }
#pragma unroll
    for (int e = 0; e < E_NUM; e++) {
        float v = acc[e];
        v += __shfl_down_sync(0xffffffffu, v, 16);
        v += __shfl_down_sync(0xffffffffu, v, 8);
        v += __shfl_down_sync(0xffffffffu, v, 4);
        v += __shfl_down_sync(0xffffffffu, v, 2);
        v += __shfl_down_sync(0xffffffffu, v, 1);
        acc[e] = v;  // valid on lane 0
    }
    if (lane == 0) {
        float logit[E_NUM];
#pragma unroll
        for (int e = 0; e < E_NUM; e++) logit[e] = acc[e] + gb[e];
        // top-1 (first index on ties, matching jax.lax.top_k stability)
        int i0 = 0; float m0 = logit[0];
#pragma unroll
        for (int e = 1; e < E_NUM; e++) if (logit[e] > m0) { m0 = logit[e]; i0 = e; }
        int i1 = -1; float m1 = -3.0e38f;
#pragma unroll
        for (int e = 0; e < E_NUM; e++)
            if (e != i0 && logit[e] > m1) { m1 = logit[e]; i1 = e; }
        float z = expf(m1 - m0);     // <= 1
        float w0 = 1.f / (1.f + z);
        float w1 = z * w0;
        g_eid[t * 2 + 0] = i0; g_eid[t * 2 + 1] = i1;
        g_gw[t * 2 + 0] = w0;  g_gw[t * 2 + 1] = w1;
        atomicAdd(&g_counts[i0], 1);
        atomicAdd(&g_counts[i1], 1);
    }
}

// ---------------- scan: 128-aligned per-expert segment offsets ----------------
__global__ void k_scan() {
    if (threadIdx.x == 0) {
        int off = 0;
        g_poff[0] = 0;
        for (int e = 0; e < E_NUM; e++) {
            off += (g_counts[e] + 127) & ~127;
            g_poff[e + 1] = off;
        }
    }
}

// ---------------- scatter tokens into per-expert segments ----------------
__global__ void k_scatter() {
    int t = blockIdx.x * blockDim.x + threadIdx.x;
    if (t >= T_TOK) return;
#pragma unroll
    for (int k = 0; k < 2; k++) {
        int e = g_eid[t * 2 + k];
        int pos = atomicAdd(&g_cursor[e], 1);
        int row = g_poff[e] + pos;
        g_rowtok[row] = t;
        g_tokrow[t * 2 + k] = row;
    }
}

// ---------------- grouped GEMM: 128x128 tiles, 8x8 per thread, fp32 ----------------
// GATHER=true  : GEMM1  relu( gather(x) @ w1[e] + b1[e] ) -> g_h
// GATHER=false : GEMM2  ( g_h @ w2[e] + b2[e] )           -> g_eout
template <int KDIM, int NDIM, bool GATHER, bool RELU>
__global__ __launch_bounds__(256, 2)
void k_gemm(const float* __restrict__ Ax, const float* __restrict__ W,
            const float* __restrict__ bias) {
    int r0 = blockIdx.x * 128;
    if (r0 >= g_poff[E_NUM]) return;
    int e = 0;
#pragma unroll
    for (int i = 1; i < E_NUM; i++) if (r0 >= g_poff[i]) e = i;

    const float* Wb = W + (size_t)e * KDIM * NDIM;
    int n0 = blockIdx.y * 128;
    int tid = threadIdx.x;

    __shared__ float As[8][128];
    __shared__ float Bs[8][128];

    int arow = tid >> 1;           // 0..127
    int acol = (tid & 1) * 4;      // 0 or 4
    int brow = tid >> 5;           // 0..7
    int bcol = (tid & 31) * 4;     // 0..124

    const float* Aptr;
    if (GATHER) {
        int tok = g_rowtok[r0 + arow];
        Aptr = (tok >= 0) ? (Ax + (size_t)tok * KDIM) : nullptr;
    } else {
        Aptr = g_h + (size_t)(r0 + arow) * KDIM;
    }

    int ty = tid >> 4, tx = tid & 15;
    float acc[8][8];
#pragma unroll
    for (int i = 0; i < 8; i++)
#pragma unroll
        for (int j = 0; j < 8; j++) acc[i][j] = 0.f;

    for (int kk = 0; kk < KDIM; kk += 8) {
        float4 av = make_float4(0.f, 0.f, 0.f, 0.f);
        if (!GATHER || Aptr) av = *(const float4*)(Aptr + kk + acol);
        As[acol + 0][arow] = av.x;
        As[acol + 1][arow] = av.y;
        As[acol + 2][arow] = av.z;
        As[acol + 3][arow] = av.w;
        *(float4*)&Bs[brow][bcol] =
            *(const float4*)(Wb + (size_t)(kk + brow) * NDIM + n0 + bcol);
        __syncthreads();
#pragma unroll
        for (int k = 0; k < 8; k++) {
            float am[8], bn[8];
            *(float4*)&am[0] = *(const float4*)&As[k][ty * 8];
            *(float4*)&am[4] = *(const float4*)&As[k][ty * 8 + 4];
            *(float4*)&bn[0] = *(const float4*)&Bs[k][tx * 8];
            *(float4*)&bn[4] = *(const float4*)&Bs[k][tx * 8 + 4];
#pragma unroll
            for (int i = 0; i < 8; i++)
#pragma unroll
                for (int j = 0; j < 8; j++) acc[i][j] += am[i] * bn[j];
        }
        __syncthreads();
    }

    float bv[8];
#pragma unroll
    for (int j = 0; j < 8; j++) bv[j] = bias[(size_t)e * NDIM + n0 + tx * 8 + j];

    float* C = RELU ? g_h : g_eout;
#pragma unroll
    for (int i = 0; i < 8; i++) {
        int r = r0 + ty * 8 + i;
        float o[8];
#pragma unroll
        for (int j = 0; j < 8; j++) {
            float v = acc[i][j] + bv[j];
            if (RELU) v = fmaxf(v, 0.f);
            o[j] = v;
        }
        float* cp = C + (size_t)r * NDIM + n0 + tx * 8;
        *(float4*)&cp[0] = *(float4*)&o[0];
        *(float4*)&cp[4] = *(float4*)&o[4];
    }
}

// ---------------- combine top-2 + residual + LayerNorm ----------------
__global__ void k_combine_ln(const float* __restrict__ x,
                             const float* __restrict__ gamma,
                             const float* __restrict__ beta,
                             float* __restrict__ out) {
    int warp = threadIdx.x >> 5, lane = threadIdx.x & 31;
    int t = blockIdx.x * 8 + warp;
    int row0 = g_tokrow[t * 2 + 0];
    int row1 = g_tokrow[t * 2 + 1];
    float w0 = g_gw[t * 2 + 0];
    float w1 = g_gw[t * 2 + 1];
    const float* xr = x + (size_t)t * H_DIM;
    const float* o0 = g_eout + (size_t)row0 * H_DIM;
    const float* o1 = g_eout + (size_t)row1 * H_DIM;

    float v[8];
    float s = 0.f, sq = 0.f;
#pragma unroll
    for (int j = 0; j < 8; j++) {
        int h = j * 32 + lane;
        float y = xr[h] + w0 * o0[h] + w1 * o1[h];
        v[j] = y;
        s += y;
        sq += y * y;
    }
#pragma unroll
    for (int off = 16; off > 0; off >>= 1) {
        s  += __shfl_xor_sync(0xffffffffu, s, off);
        sq += __shfl_xor_sync(0xffffffffu, sq, off);
    }
    float mu = s * (1.f / H_DIM);
    float var = sq * (1.f / H_DIM) - mu * mu;
    float rs = rsqrtf(var + 1e-5f);
    float* outr = out + (size_t)t * H_DIM;
#pragma unroll
    for (int j = 0; j < 8; j++) {
        int h = j * 32 + lane;
        outr[h] = (v[j] - mu) * rs * gamma[h] + beta[h];
    }
}

// ---------------- launch ----------------
extern "C" void kernel_launch(void* const* d_in, const int* in_sizes, int n_in,
                              void* d_out, int out_size) {
    const float* x      = (const float*)d_in[0];
    const float* gate_w = (const float*)d_in[1];
    const float* gate_b = (const float*)d_in[2];
    const float* w1     = (const float*)d_in[3];
    const float* b1     = (const float*)d_in[4];
    const float* w2     = (const float*)d_in[5];
    const float* b2     = (const float*)d_in[6];
    const float* gamma  = (const float*)d_in[7];
    const float* beta   = (const float*)d_in[8];
    float* out = (float*)d_out;

    k_init<<<(ROWS_PAD + 255) / 256, 256>>>();
    k_gate<<<T_TOK / 8, 256>>>(x, gate_w, gate_b);
    k_scan<<<1, 32>>>();
    k_scatter<<<T_TOK / 256, 256>>>();
    k_gemm<H_DIM, F_DIM, true,  true ><<<dim3(MAXT, F_DIM / 128), 256>>>(x, w1, b1);
    k_gemm<F_DIM, H_DIM, false, false><<<dim3(MAXT, H_DIM / 128), 256>>>(nullptr, w2, b2);
    k_combine_ln<<<T_TOK / 8, 256>>>(x, gamma, beta, out);
}